// round 1
// baseline (speedup 1.0000x reference)
#include <cuda_runtime.h>

#define N_NODES 512
#define NH      8
#define HD      128
#define FD      192      // hc dim = 128 + 64
#define MD      256      // MLP width
#define JT      8        // number of j tiles
#define TJ      64       // j's per tile

// ---------------- device scratch (static: no allocations) ----------------
__device__ float g_hc[N_NODES * FD];
__device__ float g_u [N_NODES * MD];           // hc[j] @ We0[8:200]
__device__ float g_v [N_NODES * MD];           // hc[i] @ We0[200:392] + be0
__device__ float g_mi_part   [JT * N_NODES * MD];
__device__ float g_shift_part[JT * N_NODES * 24];

__device__ __forceinline__ float silu_f(float v) { return v / (1.f + __expf(-v)); }

// ---------------- K1: hc = [h | head-pair sq dists]; ----------------
__global__ void hc_kernel(const float* __restrict__ x, const float* __restrict__ h) {
    int n = blockIdx.x, t = threadIdx.x;
    __shared__ float xi[24];
    if (t < 24) xi[t] = x[n * 24 + t];
    __syncthreads();
    if (t < HD) {
        g_hc[n * FD + t] = h[n * HD + t];
    } else if (t < FD) {
        int p = t - HD; int a = p >> 3, b = p & 7;
        float s = 0.f;
#pragma unroll
        for (int d = 0; d < 3; d++) { float dd = xi[a*3+d] - xi[b*3+d]; s += dd * dd; }
        g_hc[n * FD + t] = s;
    }
}

// ---------------- K2: u, v per node ----------------
__global__ void uv_kernel(const float* __restrict__ We0, const float* __restrict__ be0) {
    int n = blockIdx.x, t = threadIdx.x;   // 256 threads, t = output col
    __shared__ float hcs[FD];
    if (t < FD) hcs[t] = g_hc[n * FD + t];
    __syncthreads();
    float su = 0.f, sv = 0.f;
#pragma unroll 4
    for (int k = 0; k < FD; k++) {
        float hv = hcs[k];
        su += hv * We0[(8   + k) * MD + t];
        sv += hv * We0[(200 + k) * MD + t];
    }
    g_u[n * MD + t] = su;
    g_v[n * MD + t] = sv + be0[t];
}

// ---------------- smem-tiled 64x256x256 GEMM + silu ----------------
// C[64][256] = silu(A[64][256] @ W[256][256] + bias)
__device__ __forceinline__ void gemm256(const float* __restrict__ A,
                                        const float* __restrict__ W,
                                        const float* __restrict__ bias,
                                        float* sW, float* C, int tid) {
    int tr = tid >> 4, tc = tid & 15;      // thread computes rows tr*4..+3, cols tc*16..+15
    float acc[4][16];
#pragma unroll
    for (int m = 0; m < 4; m++)
#pragma unroll
        for (int n = 0; n < 16; n++) acc[m][n] = 0.f;

    for (int kc = 0; kc < 16; kc++) {
        __syncthreads();                    // protect sW from previous readers
#pragma unroll
        for (int p = 0; p < 4; p++) {
            int q = tid + p * 256;          // 1024 float4 total
            int row = q >> 6, col = (q & 63) * 4;
            *(float4*)&sW[row * 256 + col] =
                *(const float4*)&W[(kc * 16 + row) * 256 + col];
        }
        __syncthreads();
#pragma unroll
        for (int k = 0; k < 16; k++) {
            float a[4];
#pragma unroll
            for (int m = 0; m < 4; m++) a[m] = A[(tr * 4 + m) * 256 + kc * 16 + k];
#pragma unroll
            for (int g = 0; g < 4; g++) {
                float4 b = *(const float4*)&sW[k * 256 + tc * 16 + g * 4];
#pragma unroll
                for (int m = 0; m < 4; m++) {
                    acc[m][g*4+0] += a[m] * b.x;
                    acc[m][g*4+1] += a[m] * b.y;
                    acc[m][g*4+2] += a[m] * b.z;
                    acc[m][g*4+3] += a[m] * b.w;
                }
            }
        }
    }
    __syncthreads();                        // A reads done before C write (C may be reused)
#pragma unroll
    for (int m = 0; m < 4; m++) {
        int r = (tr * 4 + m) * 256;
#pragma unroll
        for (int g = 0; g < 4; g++) {
            int c = tc * 16 + g * 4;
            float4 bb = *(const float4*)&bias[c];
            float4 o;
            o.x = silu_f(acc[m][g*4+0] + bb.x);
            o.y = silu_f(acc[m][g*4+1] + bb.y);
            o.z = silu_f(acc[m][g*4+2] + bb.z);
            o.w = silu_f(acc[m][g*4+3] + bb.w);
            *(float4*)&C[r + c] = o;
        }
    }
    __syncthreads();
}

// ---------------- K3: fused edge pipeline ----------------
// block = (jt = blockIdx.x in [0,8), i = blockIdx.y in [0,512)), 256 threads
__global__ __launch_bounds__(256, 1)
void edge_kernel(const float* __restrict__ x,
                 const float* __restrict__ We0,
                 const float* __restrict__ We1, const float* __restrict__ be1,
                 const float* __restrict__ Winf, const float* __restrict__ binf,
                 const float* __restrict__ Wx0, const float* __restrict__ bx0,
                 const float* __restrict__ Wx1, const float* __restrict__ bx1,
                 const float* __restrict__ Wxo, const float* __restrict__ bxo) {
    extern __shared__ float smem[];
    float* sA    = smem;                   // 16384
    float* sB    = sA  + TJ * MD;          // 16384
    float* sW    = sB  + TJ * MD;          // 4096
    float* xs_j  = sW  + 16 * MD;          // 1536
    float* sqn_s = xs_j + TJ * 24;         // 512
    float* red   = sqn_s + TJ * 8;         // 256
    float* e_s   = red  + 256;             // 64
    float* px_s  = e_s  + TJ;              // 512
    float* xs_i  = px_s + TJ * 8;          // 24 (+pad)

    int jt = blockIdx.x, i = blockIdx.y;
    int j0 = jt * TJ;
    int tid = threadIdx.x;
    int tr = tid >> 4, tc = tid & 15;

    // --- geometry ---
    if (tid < 24) xs_i[tid] = x[i * 24 + tid];
    for (int q = tid; q < TJ * 24; q += 256) xs_j[q] = x[j0 * 24 + q];
    __syncthreads();
    for (int q = tid; q < TJ * 8; q += 256) {
        int jl = q >> 3, hh = q & 7;
        float s = 0.f;
#pragma unroll
        for (int d = 0; d < 3; d++) {
            float dd = xs_j[jl*24 + hh*3 + d] - xs_i[hh*3 + d];
            s += dd * dd;
        }
        sqn_s[q] = s;
    }
    // We0 rows 0..7 (sqn part) into sW
    for (int q = tid; q < 8 * MD; q += 256) sW[q] = We0[q];
    __syncthreads();

    // --- A1 = silu(sqn @ We0[0:8] + u[j] + v[i] (incl be0)) ---
#pragma unroll
    for (int m = 0; m < 4; m++) {
        int jl = tr * 4 + m, j = j0 + jl;
#pragma unroll
        for (int g = 0; g < 4; g++) {
#pragma unroll
            for (int e = 0; e < 4; e++) {
                int c = tc * 16 + g * 4 + e;
                float a = g_u[j * MD + c] + g_v[i * MD + c];
#pragma unroll
                for (int t8 = 0; t8 < 8; t8++)
                    a += sqn_s[jl * 8 + t8] * sW[t8 * 256 + c];
                sA[jl * 256 + c] = silu_f(a);
            }
        }
    }

    // --- GEMM1: m = silu(A1 @ We1 + be1) -> sB ---
    gemm256(sA, We1, be1, sW, sB, tid);

    // mask self-edge row of m (matches reference m *= off)
    if (i >= j0 && i < j0 + TJ) sB[(i - j0) * 256 + tid] = 0.f;
    sW[tid] = Winf[tid];                   // Winf into smem
    __syncthreads();

    // --- gate e[j] = sigmoid(m . Winf + binf) * off ---
    {
        int jl = tid >> 2, q = tid & 3;
        float p = 0.f;
#pragma unroll 4
        for (int k = q * 64; k < q * 64 + 64; k++) p += sB[jl * 256 + k] * sW[k];
        red[tid] = p;
        __syncthreads();
        if (q == 0) {
            float s = red[tid] + red[tid+1] + red[tid+2] + red[tid+3] + binf[0];
            e_s[jl] = (j0 + jl == i) ? 0.f : 1.f / (1.f + __expf(-s));
        }
    }
    __syncthreads();

    // --- m_i partial: sum_j m[j][c] * e[j] ---
    {
        float acc = 0.f;
#pragma unroll 4
        for (int jl = 0; jl < TJ; jl++) acc += sB[jl * 256 + tid] * e_s[jl];
        g_mi_part[(jt * N_NODES + i) * MD + tid] = acc;
    }

    // --- phi_x: two more GEMMs ---
    gemm256(sB, Wx0, bx0, sW, sA, tid);
    gemm256(sA, Wx1, bx1, sW, sB, tid);

    // --- px = s2 @ Wxo + bxo  (linear, no activation) ---
    for (int p = 0; p < 2; p++) {
        int o = tid + p * 256;
        int jl = o >> 3, hh = o & 7;
        float a = bxo[hh];
#pragma unroll 4
        for (int k = 0; k < 256; k++) a += sB[jl * 256 + k] * Wxo[k * 8 + hh];
        px_s[o] = a;
    }
    __syncthreads();

    // --- shift partial: sum_j (dn/norm) * px  (self-edge: dn = 0 automatically) ---
    if (tid < 24) {
        int hh = tid / 3, d = tid % 3;
        float acc = 0.f;
        for (int jl = 0; jl < TJ; jl++) {
            float dn  = xs_j[jl*24 + hh*3 + d] - xs_i[hh*3 + d];
            float nrm = sqrtf(sqn_s[jl*8 + hh] + 1e-8f) + 1.0f;
            acc += (dn / nrm) * px_s[jl * 8 + hh];
        }
        g_shift_part[(jt * N_NODES + i) * 24 + tid] = acc;
    }
}

// ---------------- K4: per-node phi_h with residual ----------------
__global__ void hnode_kernel(const float* __restrict__ h,
                             const float* __restrict__ Wh0, const float* __restrict__ bh0,
                             const float* __restrict__ Wh1, const float* __restrict__ bh1,
                             const float* __restrict__ Who, const float* __restrict__ bho,
                             float* __restrict__ out) {
    int n = blockIdx.x, t = threadIdx.x;   // 256 threads
    __shared__ float sin_s[384];
    __shared__ float s1[256];
    __shared__ float s2[256];
    // reduce m_i partials
    float mi = 0.f;
#pragma unroll
    for (int p = 0; p < JT; p++) mi += g_mi_part[(p * N_NODES + n) * MD + t];
    sin_s[t] = mi;
    if (t < HD) sin_s[256 + t] = h[n * HD + t];
    __syncthreads();
    // layer 1: 384 -> 256, silu
    {
        float a0=0,a1=0,a2=0,a3=0;
        for (int k = 0; k < 384; k += 4) {
            a0 += sin_s[k  ] * Wh0[(k  ) * 256 + t];
            a1 += sin_s[k+1] * Wh0[(k+1) * 256 + t];
            a2 += sin_s[k+2] * Wh0[(k+2) * 256 + t];
            a3 += sin_s[k+3] * Wh0[(k+3) * 256 + t];
        }
        s1[t] = silu_f(a0 + a1 + a2 + a3 + bh0[t]);
    }
    __syncthreads();
    // layer 2: 256 -> 256, silu
    {
        float a0=0,a1=0,a2=0,a3=0;
        for (int k = 0; k < 256; k += 4) {
            a0 += s1[k  ] * Wh1[(k  ) * 256 + t];
            a1 += s1[k+1] * Wh1[(k+1) * 256 + t];
            a2 += s1[k+2] * Wh1[(k+2) * 256 + t];
            a3 += s1[k+3] * Wh1[(k+3) * 256 + t];
        }
        s2[t] = silu_f(a0 + a1 + a2 + a3 + bh1[t]);
    }
    __syncthreads();
    // layer 3: 256 -> 128, linear, residual
    if (t < HD) {
        float a0=0,a1=0,a2=0,a3=0;
        for (int k = 0; k < 256; k += 4) {
            a0 += s2[k  ] * Who[(k  ) * 128 + t];
            a1 += s2[k+1] * Who[(k+1) * 128 + t];
            a2 += s2[k+2] * Who[(k+2) * 128 + t];
            a3 += s2[k+3] * Who[(k+3) * 128 + t];
        }
        out[12288 + n * HD + t] = h[n * HD + t] + a0 + a1 + a2 + a3 + bho[t];
    }
}

// ---------------- K5: x_new = x + shift/(N-1) ----------------
__global__ void xout_kernel(const float* __restrict__ x, float* __restrict__ out) {
    int idx = blockIdx.x * blockDim.x + threadIdx.x;
    if (idx < N_NODES * 24) {
        float s = 0.f;
#pragma unroll
        for (int p = 0; p < JT; p++) s += g_shift_part[p * N_NODES * 24 + idx];
        out[idx] = x[idx] + s / (float)(N_NODES - 1);
    }
}

// ---------------- launch ----------------
extern "C" void kernel_launch(void* const* d_in, const int* in_sizes, int n_in,
                              void* d_out, int out_size) {
    const float* x    = (const float*)d_in[0];
    const float* h    = (const float*)d_in[1];
    const float* We0  = (const float*)d_in[2];
    const float* be0  = (const float*)d_in[3];
    const float* We1  = (const float*)d_in[4];
    const float* be1  = (const float*)d_in[5];
    const float* Winf = (const float*)d_in[6];
    const float* binf = (const float*)d_in[7];
    const float* Wx0  = (const float*)d_in[8];
    const float* bx0  = (const float*)d_in[9];
    const float* Wx1  = (const float*)d_in[10];
    const float* bx1  = (const float*)d_in[11];
    const float* Wxo  = (const float*)d_in[12];
    const float* bxo  = (const float*)d_in[13];
    const float* Wh0  = (const float*)d_in[14];
    const float* bh0  = (const float*)d_in[15];
    const float* Wh1  = (const float*)d_in[16];
    const float* bh1  = (const float*)d_in[17];
    const float* Who  = (const float*)d_in[18];
    const float* bho  = (const float*)d_in[19];
    float* out = (float*)d_out;

    // dynamic smem for edge kernel: 39776 floats
    const int EDGE_SMEM = (16384 + 16384 + 4096 + 1536 + 512 + 256 + 64 + 512 + 32) * 4;
    cudaFuncSetAttribute(edge_kernel, cudaFuncAttributeMaxDynamicSharedMemorySize, EDGE_SMEM);

    hc_kernel<<<N_NODES, 256>>>(x, h);
    uv_kernel<<<N_NODES, 256>>>(We0, be0);
    edge_kernel<<<dim3(JT, N_NODES), 256, EDGE_SMEM>>>(
        x, We0, We1, be1, Winf, binf, Wx0, bx0, Wx1, bx1, Wxo, bxo);
    hnode_kernel<<<N_NODES, 256>>>(h, Wh0, bh0, Wh1, bh1, Who, bho, out);
    xout_kernel<<<48, 256>>>(x, out);
}

// round 2
// speedup vs baseline: 3.4613x; 3.4613x over previous
#include <cuda_runtime.h>
#include <cstdint>

#define N_NODES 512
#define NH      8
#define HD      128
#define FD      192
#define MD      256
#define JT      8
#define TJ      64
#define SA_STR  260     // A/C smem row stride (== 4 mod 32 -> conflict-free A frags)
#define SW_STR  264     // W stage row stride  (== 8 mod 32 -> conflict-free B frags)

// ---------------- device scratch ----------------
__device__ float g_hc[N_NODES * FD];
__device__ float g_u [N_NODES * MD];
__device__ float g_v [N_NODES * MD];
__device__ float g_mi_part   [JT * N_NODES * MD];
__device__ float g_shift_part[JT * N_NODES * 24];

__device__ __forceinline__ float silu_f(float v) { return v / (1.f + __expf(-v)); }

__device__ __forceinline__ float tf32r(float x) {
    uint32_t u;
    asm("cvt.rna.tf32.f32 %0, %1;" : "=r"(u) : "f"(x));
    return __uint_as_float(u);
}
__device__ __forceinline__ uint32_t f2u(float x) { return __float_as_uint(x); }

__device__ __forceinline__ void mma_tf32(float* d, uint32_t a0, uint32_t a1,
                                         uint32_t a2, uint32_t a3,
                                         uint32_t b0, uint32_t b1) {
    asm volatile("mma.sync.aligned.m16n8k8.row.col.f32.tf32.tf32.f32 "
                 "{%0,%1,%2,%3}, {%4,%5,%6,%7}, {%8,%9}, {%0,%1,%2,%3};\n"
                 : "+f"(d[0]), "+f"(d[1]), "+f"(d[2]), "+f"(d[3])
                 : "r"(a0), "r"(a1), "r"(a2), "r"(a3), "r"(b0), "r"(b1));
}

// ---------------- K1: hc = [h | head-pair sq dists] ----------------
__global__ void hc_kernel(const float* __restrict__ x, const float* __restrict__ h) {
    int n = blockIdx.x, t = threadIdx.x;
    __shared__ float xi[24];
    if (t < 24) xi[t] = x[n * 24 + t];
    __syncthreads();
    if (t < HD) {
        g_hc[n * FD + t] = h[n * HD + t];
    } else if (t < FD) {
        int p = t - HD; int a = p >> 3, b = p & 7;
        float s = 0.f;
#pragma unroll
        for (int d = 0; d < 3; d++) { float dd = xi[a*3+d] - xi[b*3+d]; s += dd * dd; }
        g_hc[n * FD + t] = s;
    }
}

// ---------------- K2: u, v per node ----------------
__global__ void uv_kernel(const float* __restrict__ We0, const float* __restrict__ be0) {
    int n = blockIdx.x, t = threadIdx.x;
    __shared__ float hcs[FD];
    if (t < FD) hcs[t] = g_hc[n * FD + t];
    __syncthreads();
    float su = 0.f, sv = 0.f;
#pragma unroll 4
    for (int k = 0; k < FD; k++) {
        float hv = hcs[k];
        su += hv * We0[(8   + k) * MD + t];
        sv += hv * We0[(200 + k) * MD + t];
    }
    g_u[n * MD + t] = su;
    g_v[n * MD + t] = sv + be0[t];
}

// ---------------- tensor-core 64x256x256 GEMM + silu (tf32) ----------------
// sC[64 x 256 (stride SA_STR)] = tf32round(silu(sA @ Wg + bias))
// Wg: global 256x256 row-major fp32 (rounded during staging).
__device__ __forceinline__ void gemm_tc(const float* __restrict__ sA,
                                        const float* __restrict__ Wg,
                                        const float* __restrict__ bias,
                                        float* sWs, float* sC, int tid) {
    int lane = tid & 31, w = tid >> 5;
    int g = lane >> 2, t = lane & 3;
    int n_base = w * 32;

    float acc[4][4][4];
#pragma unroll
    for (int mt = 0; mt < 4; mt++)
#pragma unroll
        for (int nt = 0; nt < 4; nt++)
#pragma unroll
            for (int r = 0; r < 4; r++) acc[mt][nt][r] = 0.f;

    for (int kc = 0; kc < 8; kc++) {            // 8 chunks of 32 k-rows
        __syncthreads();                         // protect sWs from prior readers
#pragma unroll
        for (int p = 0; p < 8; p++) {
            int q = tid + p * 256;               // 2048 float4 slots
            int row = q >> 6, c4 = (q & 63) << 2;
            float4 v = *(const float4*)&Wg[(kc * 32 + row) * 256 + c4];
            v.x = tf32r(v.x); v.y = tf32r(v.y); v.z = tf32r(v.z); v.w = tf32r(v.w);
            *(float4*)&sWs[row * SW_STR + c4] = v;
        }
        __syncthreads();
#pragma unroll
        for (int ks = 0; ks < 4; ks++) {
            int k0 = ks * 8;
            uint32_t b0[4], b1[4];
#pragma unroll
            for (int nt = 0; nt < 4; nt++) {
                int nc = n_base + nt * 8 + g;
                b0[nt] = f2u(sWs[(k0 + t)     * SW_STR + nc]);
                b1[nt] = f2u(sWs[(k0 + t + 4) * SW_STR + nc]);
            }
#pragma unroll
            for (int mt = 0; mt < 4; mt++) {
                const float* Ap = &sA[(mt * 16 + g) * SA_STR + kc * 32 + k0 + t];
                uint32_t a0 = f2u(Ap[0]);
                uint32_t a1 = f2u(Ap[8 * SA_STR]);
                uint32_t a2 = f2u(Ap[4]);
                uint32_t a3 = f2u(Ap[8 * SA_STR + 4]);
#pragma unroll
                for (int nt = 0; nt < 4; nt++)
                    mma_tf32(acc[mt][nt], a0, a1, a2, a3, b0[nt], b1[nt]);
            }
        }
    }
    // epilogue: bias + silu + tf32 round, write to sC
#pragma unroll
    for (int mt = 0; mt < 4; mt++) {
        int r0 = (mt * 16 + g) * SA_STR;
        int r1 = r0 + 8 * SA_STR;
#pragma unroll
        for (int nt = 0; nt < 4; nt++) {
            int col = n_base + nt * 8 + 2 * t;
            float2 bb = *(const float2*)&bias[col];
            float v0 = tf32r(silu_f(acc[mt][nt][0] + bb.x));
            float v1 = tf32r(silu_f(acc[mt][nt][1] + bb.y));
            float v2 = tf32r(silu_f(acc[mt][nt][2] + bb.x));
            float v3 = tf32r(silu_f(acc[mt][nt][3] + bb.y));
            *(float2*)&sC[r0 + col] = make_float2(v0, v1);
            *(float2*)&sC[r1 + col] = make_float2(v2, v3);
        }
    }
}

// ---------------- K3: fused edge pipeline (tensor-core) ----------------
__global__ __launch_bounds__(256, 1)
void edge_kernel(const float* __restrict__ x,
                 const float* __restrict__ We0,
                 const float* __restrict__ We1, const float* __restrict__ be1,
                 const float* __restrict__ Winf, const float* __restrict__ binf,
                 const float* __restrict__ Wx0, const float* __restrict__ bx0,
                 const float* __restrict__ Wx1, const float* __restrict__ bx1,
                 const float* __restrict__ Wxo, const float* __restrict__ bxo) {
    extern __shared__ float smem[];
    float* sA    = smem;                        // 64*260 = 16640
    float* sB    = sA   + 64 * SA_STR;          // 16640
    float* sWs   = sB   + 64 * SA_STR;          // 32*264 = 8448
    float* xs_j  = sWs  + 32 * SW_STR;          // 1536
    float* sqn_s = xs_j + TJ * 24;              // 512
    float* red   = sqn_s + TJ * 8;              // 256
    float* e_s   = red  + 256;                  // 64
    float* px_s  = e_s  + TJ;                   // 512
    float* xs_i  = px_s + TJ * 8;               // 32

    int jt = blockIdx.x, i = blockIdx.y;
    int j0 = jt * TJ;
    int tid = threadIdx.x;

    // --- geometry + We0[0:8] stage ---
    if (tid < 24) xs_i[tid] = x[i * 24 + tid];
    for (int q = tid; q < TJ * 24; q += 256) xs_j[q] = x[j0 * 24 + q];
    for (int q = tid; q < 8 * MD; q += 256) sWs[q] = We0[q];
    __syncthreads();
    for (int q = tid; q < TJ * 8; q += 256) {
        int jl = q >> 3, hh = q & 7;
        float s = 0.f;
#pragma unroll
        for (int d = 0; d < 3; d++) {
            float dd = xs_j[jl*24 + hh*3 + d] - xs_i[hh*3 + d];
            s += dd * dd;
        }
        sqn_s[q] = s;
    }
    __syncthreads();

    // --- A1 = tf32(silu(sqn @ We0[0:8] + u[j] + v[i])) ---
    {
        int c = tid;
        float vv = g_v[i * MD + c];
        float w8[8];
#pragma unroll
        for (int t8 = 0; t8 < 8; t8++) w8[t8] = sWs[t8 * 256 + c];
        for (int jl = 0; jl < TJ; jl++) {
            float a = vv + g_u[(j0 + jl) * MD + c];
#pragma unroll
            for (int t8 = 0; t8 < 8; t8++) a += sqn_s[jl * 8 + t8] * w8[t8];
            sA[jl * SA_STR + c] = tf32r(silu_f(a));
        }
    }

    // --- GEMM1: m = silu(A1 @ We1 + be1) -> sB ---
    gemm_tc(sA, We1, be1, sWs, sB, tid);
    __syncthreads();

    // mask self-edge row of m
    if (i >= j0 && i < j0 + TJ) sB[(i - j0) * SA_STR + tid] = 0.f;
    __syncthreads();

    // --- gate e[j] = sigmoid(m . Winf + binf) * off ---
    {
        int jl = tid >> 2, q = tid & 3;
        float p = 0.f;
#pragma unroll 4
        for (int k = q * 64; k < q * 64 + 64; k++) p += sB[jl * SA_STR + k] * Winf[k];
        red[tid] = p;
        __syncthreads();
        if (q == 0) {
            float s = red[tid] + red[tid+1] + red[tid+2] + red[tid+3] + binf[0];
            e_s[jl] = (j0 + jl == i) ? 0.f : 1.f / (1.f + __expf(-s));
        }
    }
    __syncthreads();

    // --- m_i partial ---
    {
        float acc = 0.f;
#pragma unroll 4
        for (int jl = 0; jl < TJ; jl++) acc += sB[jl * SA_STR + tid] * e_s[jl];
        g_mi_part[(jt * N_NODES + i) * MD + tid] = acc;
    }

    // --- phi_x GEMMs ---
    gemm_tc(sB, Wx0, bx0, sWs, sA, tid);   // first sync inside guards m_i reads
    gemm_tc(sA, Wx1, bx1, sWs, sB, tid);
    __syncthreads();

    // stage Wxo (256x8) into sWs
    for (int q = tid; q < 2048; q += 256) sWs[q] = Wxo[q];
    __syncthreads();

    // --- px = s2 @ Wxo + bxo ---
    for (int p = 0; p < 2; p++) {
        int o = tid + p * 256;
        int jl = o >> 3, hh = o & 7;
        float a = bxo[hh];
#pragma unroll 4
        for (int k = 0; k < 256; k++) a += sB[jl * SA_STR + k] * sWs[k * 8 + hh];
        px_s[o] = a;
    }
    __syncthreads();

    // --- shift partial ---
    if (tid < 24) {
        int hh = tid / 3, d = tid % 3;
        float acc = 0.f;
        for (int jl = 0; jl < TJ; jl++) {
            float dn  = xs_j[jl*24 + hh*3 + d] - xs_i[hh*3 + d];
            float nrm = sqrtf(sqn_s[jl*8 + hh] + 1e-8f) + 1.0f;
            acc += (dn / nrm) * px_s[jl * 8 + hh];
        }
        g_shift_part[(jt * N_NODES + i) * 24 + tid] = acc;
    }
}

// ---------------- K4: phi_h, 4 nodes per block ----------------
__global__ void hnode_kernel(const float* __restrict__ h,
                             const float* __restrict__ Wh0, const float* __restrict__ bh0,
                             const float* __restrict__ Wh1, const float* __restrict__ bh1,
                             const float* __restrict__ Who, const float* __restrict__ bho,
                             float* __restrict__ out) {
    int nb = blockIdx.x * 4, t = threadIdx.x;
    __shared__ float sin_s[4 * 384];
    __shared__ float s1[4 * 256];
    __shared__ float s2[4 * 256];
#pragma unroll
    for (int n = 0; n < 4; n++) {
        float mi = 0.f;
#pragma unroll
        for (int p = 0; p < JT; p++) mi += g_mi_part[(p * N_NODES + nb + n) * MD + t];
        sin_s[n * 384 + t] = mi;
        if (t < HD) sin_s[n * 384 + 256 + t] = h[(nb + n) * HD + t];
    }
    __syncthreads();
    {
        float a0 = bh0[t], a1 = a0, a2 = a0, a3 = a0;
#pragma unroll 4
        for (int k = 0; k < 384; k++) {
            float w = Wh0[k * 256 + t];
            a0 += sin_s[k] * w; a1 += sin_s[384 + k] * w;
            a2 += sin_s[768 + k] * w; a3 += sin_s[1152 + k] * w;
        }
        s1[t] = silu_f(a0); s1[256 + t] = silu_f(a1);
        s1[512 + t] = silu_f(a2); s1[768 + t] = silu_f(a3);
    }
    __syncthreads();
    {
        float a0 = bh1[t], a1 = a0, a2 = a0, a3 = a0;
#pragma unroll 4
        for (int k = 0; k < 256; k++) {
            float w = Wh1[k * 256 + t];
            a0 += s1[k] * w; a1 += s1[256 + k] * w;
            a2 += s1[512 + k] * w; a3 += s1[768 + k] * w;
        }
        s2[t] = silu_f(a0); s2[256 + t] = silu_f(a1);
        s2[512 + t] = silu_f(a2); s2[768 + t] = silu_f(a3);
    }
    __syncthreads();
    if (t < HD) {
        float a0 = bho[t], a1 = a0, a2 = a0, a3 = a0;
#pragma unroll 4
        for (int k = 0; k < 256; k++) {
            float w = Who[k * 128 + t];
            a0 += s2[k] * w; a1 += s2[256 + k] * w;
            a2 += s2[512 + k] * w; a3 += s2[768 + k] * w;
        }
        out[12288 + (nb + 0) * HD + t] = h[(nb + 0) * HD + t] + a0;
        out[12288 + (nb + 1) * HD + t] = h[(nb + 1) * HD + t] + a1;
        out[12288 + (nb + 2) * HD + t] = h[(nb + 2) * HD + t] + a2;
        out[12288 + (nb + 3) * HD + t] = h[(nb + 3) * HD + t] + a3;
    }
}

// ---------------- K5: x_new ----------------
__global__ void xout_kernel(const float* __restrict__ x, float* __restrict__ out) {
    int idx = blockIdx.x * blockDim.x + threadIdx.x;
    if (idx < N_NODES * 24) {
        float s = 0.f;
#pragma unroll
        for (int p = 0; p < JT; p++) s += g_shift_part[p * N_NODES * 24 + idx];
        out[idx] = x[idx] + s / (float)(N_NODES - 1);
    }
}

// ---------------- launch ----------------
extern "C" void kernel_launch(void* const* d_in, const int* in_sizes, int n_in,
                              void* d_out, int out_size) {
    const float* x    = (const float*)d_in[0];
    const float* h    = (const float*)d_in[1];
    const float* We0  = (const float*)d_in[2];
    const float* be0  = (const float*)d_in[3];
    const float* We1  = (const float*)d_in[4];
    const float* be1  = (const float*)d_in[5];
    const float* Winf = (const float*)d_in[6];
    const float* binf = (const float*)d_in[7];
    const float* Wx0  = (const float*)d_in[8];
    const float* bx0  = (const float*)d_in[9];
    const float* Wx1  = (const float*)d_in[10];
    const float* bx1  = (const float*)d_in[11];
    const float* Wxo  = (const float*)d_in[12];
    const float* bxo  = (const float*)d_in[13];
    const float* Wh0  = (const float*)d_in[14];
    const float* bh0  = (const float*)d_in[15];
    const float* Wh1  = (const float*)d_in[16];
    const float* bh1  = (const float*)d_in[17];
    const float* Who  = (const float*)d_in[18];
    const float* bho  = (const float*)d_in[19];
    float* out = (float*)d_out;

    const int EDGE_SMEM = (2 * 64 * SA_STR + 32 * SW_STR +
                           TJ * 24 + TJ * 8 + 256 + TJ + TJ * 8 + 32) * 4;
    cudaFuncSetAttribute(edge_kernel, cudaFuncAttributeMaxDynamicSharedMemorySize, EDGE_SMEM);

    hc_kernel<<<N_NODES, 256>>>(x, h);
    uv_kernel<<<N_NODES, 256>>>(We0, be0);
    edge_kernel<<<dim3(JT, N_NODES), 256, EDGE_SMEM>>>(
        x, We0, We1, be1, Winf, binf, Wx0, bx0, Wx1, bx1, Wxo, bxo);
    hnode_kernel<<<N_NODES / 4, 256>>>(h, Wh0, bh0, Wh1, bh1, Who, bho, out);
    xout_kernel<<<48, 256>>>(x, out);
}

// round 5
// speedup vs baseline: 5.4324x; 1.5695x over previous
#include <cuda_runtime.h>
#include <cuda_fp16.h>
#include <cstdint>

#define N_NODES 512
#define HD      128
#define FD      192
#define MD      256
#define JT      8
#define TJ      64
#define SA_STRH 264      // sA row stride in halves (132 words == 4 mod 32: conflict-free frags)
#define STG_STRH 40      // stage row stride in halves (20 words == 20 mod 32: conflict-free)

// ---------------- device scratch ----------------
__device__ float g_hc[N_NODES * FD];
__device__ float g_u [N_NODES * MD];
__device__ float g_v [N_NODES * MD];
__device__ float g_mi_part   [JT * N_NODES * MD];
__device__ float g_shift_part[JT * N_NODES * 24];
// pre-transposed half weights: Wt[n][k] = half(W[k][n])
__device__ __half g_We1h[MD * MD];
__device__ __half g_Wx0h[MD * MD];
__device__ __half g_Wx1h[MD * MD];

__device__ __forceinline__ float silu_f(float v) { return v / (1.f + __expf(-v)); }

__device__ __forceinline__ uint32_t smem_u32(const void* p) {
    uint32_t a;
    asm("{ .reg .u64 t; cvta.to.shared.u64 t, %1; cvt.u32.u64 %0, t; }" : "=r"(a) : "l"(p));
    return a;
}

__device__ __forceinline__ void mma_fp16(float* d, uint32_t a0, uint32_t a1,
                                         uint32_t a2, uint32_t a3,
                                         uint32_t b0, uint32_t b1) {
    asm volatile("mma.sync.aligned.m16n8k16.row.col.f32.f16.f16.f32 "
                 "{%0,%1,%2,%3}, {%4,%5,%6,%7}, {%8,%9}, {%0,%1,%2,%3};\n"
                 : "+f"(d[0]), "+f"(d[1]), "+f"(d[2]), "+f"(d[3])
                 : "r"(a0), "r"(a1), "r"(a2), "r"(a3), "r"(b0), "r"(b1));
}

// ---------------- smem layout (byte offsets, 128-aligned) ----------------
#define SA_OFF    0        // 67584 : A/C tile [128][264] half
#define ST0_OFF   67584    // 20480 : weight stage buf 0 [256][40] half
#define ST1_OFF   88064    // 20480 : weight stage buf 1
#define AUX_OFF   108544   // 8192  : We0 rows 0..7 fp32, later Wxo fp32
#define SQN_OFF   116736   // 4096  : sqn [2][64][8] fp32
#define XSJ_OFF   120832   // 6144  : x_j [64][24]
#define XSI_OFF   126976   // 192   : x_i [2][24]
#define WINF_OFF  127168   // 1024
#define RED_OFF   128192   // 512   : gate partials [128]
#define ES_OFF    128704   // 512   : e [128]
#define PXP_OFF   129216   // 8192  : px partials [2][128][8]
#define EDGE_SMEM_BYTES (137408 + 128)

// ---------------- K0: transpose + halve weights ----------------
__global__ void prep_kernel(const float* __restrict__ We1, const float* __restrict__ Wx0,
                            const float* __restrict__ Wx1) {
    __shared__ float t[32][33];
    int b = blockIdx.x;            // 192 blocks
    int mat = b >> 6, tile = b & 63;
    int tk = tile >> 3, tn = tile & 7;
    const float* S = (mat == 0) ? We1 : (mat == 1) ? Wx0 : Wx1;
    __half* D = (mat == 0) ? g_We1h : (mat == 1) ? g_Wx0h : g_Wx1h;
    int r0 = threadIdx.x >> 5, c = threadIdx.x & 31;
#pragma unroll
    for (int q = 0; q < 4; q++) {
        int r = r0 + q * 8;
        t[r][c] = S[(tk * 32 + r) * 256 + tn * 32 + c];
    }
    __syncthreads();
#pragma unroll
    for (int q = 0; q < 4; q++) {
        int r = r0 + q * 8;
        D[(tn * 32 + r) * 256 + tk * 32 + c] = __float2half_rn(t[c][r]);
    }
}

// ---------------- K1: hc ----------------
__global__ void hc_kernel(const float* __restrict__ x, const float* __restrict__ h) {
    int n = blockIdx.x, t = threadIdx.x;
    __shared__ float xi[24];
    if (t < 24) xi[t] = x[n * 24 + t];
    __syncthreads();
    if (t < HD) {
        g_hc[n * FD + t] = h[n * HD + t];
    } else if (t < FD) {
        int p = t - HD; int a = p >> 3, b = p & 7;
        float s = 0.f;
#pragma unroll
        for (int d = 0; d < 3; d++) { float dd = xi[a*3+d] - xi[b*3+d]; s += dd * dd; }
        g_hc[n * FD + t] = s;
    }
}

// ---------------- K2: u, v ----------------
__global__ void uv_kernel(const float* __restrict__ We0, const float* __restrict__ be0) {
    int n = blockIdx.x, t = threadIdx.x;
    __shared__ float hcs[FD];
    if (t < FD) hcs[t] = g_hc[n * FD + t];
    __syncthreads();
    float su = 0.f, sv = 0.f;
#pragma unroll 4
    for (int k = 0; k < FD; k++) {
        float hv = hcs[k];
        su += hv * We0[(8   + k) * MD + t];
        sv += hv * We0[(200 + k) * MD + t];
    }
    g_u[n * MD + t] = su;
    g_v[n * MD + t] = sv + be0[t];
}

// ---------------- weight chunk staging: 32 k-halves for all 256 n ----------------
__device__ __forceinline__ void stage_cp(const __half* __restrict__ Wt, int kc,
                                         uint32_t dst, int tid) {
#pragma unroll
    for (int p = 0; p < 4; p++) {
        int s = tid + p * 256;                // 1024 jobs of 16B
        int n = s >> 2, q = s & 3;
        const __half* src = Wt + n * 256 + kc * 32 + q * 8;
        uint32_t d = dst + (uint32_t)(n * (STG_STRH * 2) + q * 16);
        asm volatile("cp.async.cg.shared.global [%0], [%1], 16;" :: "r"(d), "l"(src));
    }
}

// ---------------- fp16 tensor GEMM: acc[128x256] = sA[128x256] @ Wt^T ----------------
__device__ __forceinline__ void gemm_fp16(const __half* __restrict__ sA,
                                          const __half* __restrict__ stp0,
                                          const __half* __restrict__ stp1,
                                          uint32_t st0, uint32_t st1,
                                          const __half* __restrict__ Wt,
                                          float acc[8][4][4], int tid) {
    int lane = tid & 31, w = tid >> 5;
    int g = lane >> 2, t = lane & 3;
#pragma unroll
    for (int mt = 0; mt < 8; mt++)
#pragma unroll
        for (int nt = 0; nt < 4; nt++)
#pragma unroll
            for (int e = 0; e < 4; e++) acc[mt][nt][e] = 0.f;

    stage_cp(Wt, 0, st0, tid);
    asm volatile("cp.async.commit_group;" ::: "memory");
#pragma unroll 1
    for (int s = 0; s < 8; s++) {
        if (s < 7) {
            stage_cp(Wt, s + 1, (s & 1) ? st0 : st1, tid);
            asm volatile("cp.async.commit_group;" ::: "memory");
            asm volatile("cp.async.wait_group 1;" ::: "memory");
        } else {
            asm volatile("cp.async.wait_group 0;" ::: "memory");
        }
        __syncthreads();
        const __half* stg = (s & 1) ? stp1 : stp0;
#pragma unroll
        for (int ks = 0; ks < 2; ks++) {
            int kw = s * 32 + ks * 16 + 2 * t;
            uint32_t b0[4], b1[4];
#pragma unroll
            for (int nt = 0; nt < 4; nt++) {
                int nc = w * 32 + nt * 8 + g;
                const uint32_t* bp = (const uint32_t*)(stg + nc * STG_STRH + ks * 16 + 2 * t);
                b0[nt] = bp[0];
                b1[nt] = bp[4];
            }
#pragma unroll
            for (int mt = 0; mt < 8; mt++) {
                const uint32_t* ap0 = (const uint32_t*)(sA + (mt * 16 + g) * SA_STRH + kw);
                const uint32_t* ap1 = (const uint32_t*)(sA + (mt * 16 + g + 8) * SA_STRH + kw);
                uint32_t a0 = ap0[0], a2 = ap0[4];
                uint32_t a1 = ap1[0], a3 = ap1[4];
#pragma unroll
                for (int nt = 0; nt < 4; nt++)
                    mma_fp16(acc[mt][nt], a0, a1, a2, a3, b0[nt], b1[nt]);
            }
        }
        __syncthreads();     // before next-stage overwrite / before epilogue writes sA
    }
}

// ---------------- K3: fused edge pipeline ----------------
__global__ __launch_bounds__(256, 1)
void edge_kernel(const float* __restrict__ x,
                 const float* __restrict__ We0,
                 const float* __restrict__ be1,
                 const float* __restrict__ Winf, const float* __restrict__ binf,
                 const float* __restrict__ bx0, const float* __restrict__ bx1,
                 const float* __restrict__ Wxo, const float* __restrict__ bxo) {
    extern __shared__ __align__(128) char smem[];
    __half* sA    = (__half*)(smem + SA_OFF);
    __half* stp0  = (__half*)(smem + ST0_OFF);
    __half* stp1  = (__half*)(smem + ST1_OFF);
    float* sAux  = (float*)(smem + AUX_OFF);
    float* sqn_s = (float*)(smem + SQN_OFF);
    float* xs_j  = (float*)(smem + XSJ_OFF);
    float* xs_i  = (float*)(smem + XSI_OFF);
    float* sWinf = (float*)(smem + WINF_OFF);
    float* red   = (float*)(smem + RED_OFF);
    float* e_s   = (float*)(smem + ES_OFF);
    float* pxp   = (float*)(smem + PXP_OFF);
    uint32_t sbase = smem_u32(smem);
    uint32_t st0 = sbase + ST0_OFF, st1 = sbase + ST1_OFF;

    int tid = threadIdx.x;
    int lane = tid & 31, w = tid >> 5, g = lane >> 2, t4 = lane & 3;
    int jt = blockIdx.x, ip = blockIdx.y;
    int i0 = ip * 2, i1 = i0 + 1, j0 = jt * TJ;

    // --- stage geometry + constants ---
    if (tid < 256) sWinf[tid] = Winf[tid];
    for (int q = tid; q < 8 * MD; q += 256) sAux[q] = We0[q];
    if (tid < 48) xs_i[tid] = x[i0 * 24 + tid];
    for (int q = tid; q < TJ * 24; q += 256) xs_j[q] = x[j0 * 24 + q];
    if (tid < 128) red[tid] = 0.f;
    __syncthreads();

    for (int q = tid; q < 2 * TJ * 8; q += 256) {
        int half = q >> 9, rem = q & 511, jl = rem >> 3, hh = rem & 7;
        float s = 0.f;
#pragma unroll
        for (int d = 0; d < 3; d++) {
            float dd = xs_j[jl*24 + hh*3 + d] - xs_i[half*24 + hh*3 + d];
            s += dd * dd;
        }
        sqn_s[q] = s;
    }
    __syncthreads();

    // --- A1 = half(silu(sqn @ We0[0:8] + u[j] + v[i])) ---
    {
        int c = tid;
        float v0 = g_v[i0 * MD + c], v1 = g_v[i1 * MD + c];
        float w8[8];
#pragma unroll
        for (int t8 = 0; t8 < 8; t8++) w8[t8] = sAux[t8 * 256 + c];
        for (int r = 0; r < 128; r++) {
            int half = r >> 6, jl = r & 63;
            float a = (half ? v1 : v0) + g_u[(j0 + jl) * MD + c];
#pragma unroll
            for (int t8 = 0; t8 < 8; t8++) a += sqn_s[half * 512 + jl * 8 + t8] * w8[t8];
            sA[r * SA_STRH + c] = __float2half_rn(silu_f(a));
        }
    }
    __syncthreads();
    // restage sAux with Wxo for the px phase
    for (int q = tid; q < 2048; q += 256) sAux[q] = Wxo[q];

    float acc[8][4][4];

    // ================= GEMM1: m = silu(A1 @ We1 + be1), masked =================
    gemm_fp16(sA, stp0, stp1, st0, st1, g_We1h, acc, tid);
    {
#pragma unroll
        for (int mt = 0; mt < 8; mt++) {
            int r0 = mt * 16 + g, r1 = r0 + 8;
            bool s0 = (j0 + (r0 & 63)) == ((r0 < 64) ? i0 : i1);
            bool s1 = (j0 + (r1 & 63)) == ((r1 < 64) ? i0 : i1);
            float gp0 = 0.f, gp1 = 0.f;
#pragma unroll
            for (int nt = 0; nt < 4; nt++) {
                int cn = w * 32 + nt * 8 + 2 * t4;
                float w0 = sWinf[cn], w1 = sWinf[cn + 1];
                float b0v = be1[cn], b1v = be1[cn + 1];
                float v0 = s0 ? 0.f : silu_f(acc[mt][nt][0] + b0v);
                float v1 = s0 ? 0.f : silu_f(acc[mt][nt][1] + b1v);
                float v2 = s1 ? 0.f : silu_f(acc[mt][nt][2] + b0v);
                float v3 = s1 ? 0.f : silu_f(acc[mt][nt][3] + b1v);
                *(__half2*)&sA[r0 * SA_STRH + cn] = __floats2half2_rn(v0, v1);
                *(__half2*)&sA[r1 * SA_STRH + cn] = __floats2half2_rn(v2, v3);
                gp0 += v0 * w0 + v1 * w1;
                gp1 += v2 * w0 + v3 * w1;
            }
            gp0 += __shfl_xor_sync(0xffffffff, gp0, 1);
            gp0 += __shfl_xor_sync(0xffffffff, gp0, 2);
            gp1 += __shfl_xor_sync(0xffffffff, gp1, 1);
            gp1 += __shfl_xor_sync(0xffffffff, gp1, 2);
            if (t4 == 0) { atomicAdd(&red[r0], gp0); atomicAdd(&red[r1], gp1); }
        }
    }
    __syncthreads();

    // --- gate e ---
    if (tid < 128) {
        float s = red[tid] + binf[0];
        int jj = j0 + (tid & 63), ii = (tid < 64) ? i0 : i1;
        e_s[tid] = (jj == ii) ? 0.f : 1.f / (1.f + __expf(-s));
    }
    __syncthreads();

    // --- m_i partials ---
#pragma unroll
    for (int p = 0; p < 2; p++) {
        int job = tid + p * 256;
        int c = job & 255, half = job >> 8;
        float a = 0.f;
        int rb = half * 64;
#pragma unroll 4
        for (int rr = 0; rr < 64; rr++)
            a += __half2float(sA[(rb + rr) * SA_STRH + c]) * e_s[rb + rr];
        g_mi_part[(jt * N_NODES + (half ? i1 : i0)) * MD + c] = a;
    }
    __syncthreads();

    // ================= GEMM2: s1 = silu(m @ Wx0 + bx0) =================
    gemm_fp16(sA, stp0, stp1, st0, st1, g_Wx0h, acc, tid);
#pragma unroll
    for (int mt = 0; mt < 8; mt++) {
        int r0 = mt * 16 + g, r1 = r0 + 8;
#pragma unroll
        for (int nt = 0; nt < 4; nt++) {
            int cn = w * 32 + nt * 8 + 2 * t4;
            float b0v = bx0[cn], b1v = bx0[cn + 1];
            *(__half2*)&sA[r0 * SA_STRH + cn] =
                __floats2half2_rn(silu_f(acc[mt][nt][0] + b0v), silu_f(acc[mt][nt][1] + b1v));
            *(__half2*)&sA[r1 * SA_STRH + cn] =
                __floats2half2_rn(silu_f(acc[mt][nt][2] + b0v), silu_f(acc[mt][nt][3] + b1v));
        }
    }
    __syncthreads();

    // ================= GEMM3: s2 = silu(s1 @ Wx1 + bx1) =================
    gemm_fp16(sA, stp0, stp1, st0, st1, g_Wx1h, acc, tid);
#pragma unroll
    for (int mt = 0; mt < 8; mt++) {
        int r0 = mt * 16 + g, r1 = r0 + 8;
#pragma unroll
        for (int nt = 0; nt < 4; nt++) {
            int cn = w * 32 + nt * 8 + 2 * t4;
            float b0v = bx1[cn], b1v = bx1[cn + 1];
            *(__half2*)&sA[r0 * SA_STRH + cn] =
                __floats2half2_rn(silu_f(acc[mt][nt][0] + b0v), silu_f(acc[mt][nt][1] + b1v));
            *(__half2*)&sA[r1 * SA_STRH + cn] =
                __floats2half2_rn(silu_f(acc[mt][nt][2] + b0v), silu_f(acc[mt][nt][3] + b1v));
        }
    }
    __syncthreads();

    // --- px partials: px[r] = s2[r] @ Wxo ---
    {
        int r = tid & 127, chunk = tid >> 7;
        float pa[8];
#pragma unroll
        for (int hh = 0; hh < 8; hh++) pa[hh] = 0.f;
        int c0 = chunk * 128;
        for (int c = c0; c < c0 + 128; c++) {
            float v = __half2float(sA[r * SA_STRH + c]);
#pragma unroll
            for (int hh = 0; hh < 8; hh++) pa[hh] += v * sAux[c * 8 + hh];
        }
#pragma unroll
        for (int hh = 0; hh < 8; hh++) pxp[(chunk * 128 + r) * 8 + hh] = pa[hh];
    }
    __syncthreads();
    if (tid < 128) {
#pragma unroll
        for (int hh = 0; hh < 8; hh++)
            pxp[tid * 8 + hh] = pxp[tid * 8 + hh] + pxp[(128 + tid) * 8 + hh] + bxo[hh];
    }
    __syncthreads();

    // --- shift partials ---
    if (tid < 48) {
        int half = tid / 24, q = tid % 24, hh = q / 3, d = q % 3;
        int ii = half ? i1 : i0;
        float accs = 0.f;
        for (int jl = 0; jl < TJ; jl++) {
            float dn  = xs_j[jl*24 + hh*3 + d] - xs_i[half*24 + hh*3 + d];
            float nrm = sqrtf(sqn_s[half*512 + jl*8 + hh] + 1e-8f) + 1.0f;
            accs += (dn / nrm) * pxp[(half * 64 + jl) * 8 + hh];
        }
        g_shift_part[(jt * N_NODES + ii) * 24 + q] = accs;
    }
}

// ---------------- K4: phi_h per node ----------------
__global__ void hnode_kernel(const float* __restrict__ h,
                             const float* __restrict__ Wh0, const float* __restrict__ bh0,
                             const float* __restrict__ Wh1, const float* __restrict__ bh1,
                             const float* __restrict__ Who, const float* __restrict__ bho,
                             float* __restrict__ out) {
    int n = blockIdx.x, t = threadIdx.x;
    __shared__ float sin_s[384];
    __shared__ float s1[256];
    __shared__ float s2[256];
    float mi = 0.f;
#pragma unroll
    for (int p = 0; p < JT; p++) mi += g_mi_part[(p * N_NODES + n) * MD + t];
    sin_s[t] = mi;
    if (t < HD) sin_s[256 + t] = h[n * HD + t];
    __syncthreads();
    {
        float a0=0,a1=0,a2=0,a3=0;
        for (int k = 0; k < 384; k += 4) {
            a0 += sin_s[k  ] * Wh0[(k  ) * 256 + t];
            a1 += sin_s[k+1] * Wh0[(k+1) * 256 + t];
            a2 += sin_s[k+2] * Wh0[(k+2) * 256 + t];
            a3 += sin_s[k+3] * Wh0[(k+3) * 256 + t];
        }
        s1[t] = silu_f(a0 + a1 + a2 + a3 + bh0[t]);
    }
    __syncthreads();
    {
        float a0=0,a1=0,a2=0,a3=0;
        for (int k = 0; k < 256; k += 4) {
            a0 += s1[k  ] * Wh1[(k  ) * 256 + t];
            a1 += s1[k+1] * Wh1[(k+1) * 256 + t];
            a2 += s1[k+2] * Wh1[(k+2) * 256 + t];
            a3 += s1[k+3] * Wh1[(k+3) * 256 + t];
        }
        s2[t] = silu_f(a0 + a1 + a2 + a3 + bh1[t]);
    }
    __syncthreads();
    if (t < HD) {
        float a0=0,a1=0,a2=0,a3=0;
        for (int k = 0; k < 256; k += 4) {
            a0 += s2[k  ] * Who[(k  ) * 128 + t];
            a1 += s2[k+1] * Who[(k+1) * 128 + t];
            a2 += s2[k+2] * Who[(k+2) * 128 + t];
            a3 += s2[k+3] * Who[(k+3) * 128 + t];
        }
        out[12288 + n * HD + t] = h[n * HD + t] + a0 + a1 + a2 + a3 + bho[t];
    }
}

// ---------------- K5: x_new ----------------
__global__ void xout_kernel(const float* __restrict__ x, float* __restrict__ out) {
    int idx = blockIdx.x * blockDim.x + threadIdx.x;
    if (idx < N_NODES * 24) {
        float s = 0.f;
#pragma unroll
        for (int p = 0; p < JT; p++) s += g_shift_part[p * N_NODES * 24 + idx];
        out[idx] = x[idx] + s / (float)(N_NODES - 1);
    }
}

// ---------------- launch ----------------
extern "C" void kernel_launch(void* const* d_in, const int* in_sizes, int n_in,
                              void* d_out, int out_size) {
    const float* x    = (const float*)d_in[0];
    const float* h    = (const float*)d_in[1];
    const float* We0  = (const float*)d_in[2];
    const float* be0  = (const float*)d_in[3];
    const float* We1  = (const float*)d_in[4];
    const float* be1  = (const float*)d_in[5];
    const float* Winf = (const float*)d_in[6];
    const float* binf = (const float*)d_in[7];
    const float* Wx0  = (const float*)d_in[8];
    const float* bx0  = (const float*)d_in[9];
    const float* Wx1  = (const float*)d_in[10];
    const float* bx1  = (const float*)d_in[11];
    const float* Wxo  = (const float*)d_in[12];
    const float* bxo  = (const float*)d_in[13];
    const float* Wh0  = (const float*)d_in[14];
    const float* bh0  = (const float*)d_in[15];
    const float* Wh1  = (const float*)d_in[16];
    const float* bh1  = (const float*)d_in[17];
    const float* Who  = (const float*)d_in[18];
    const float* bho  = (const float*)d_in[19];
    float* out = (float*)d_out;

    cudaFuncSetAttribute(edge_kernel, cudaFuncAttributeMaxDynamicSharedMemorySize,
                         EDGE_SMEM_BYTES);

    prep_kernel<<<192, 256>>>(We1, Wx0, Wx1);
    hc_kernel<<<N_NODES, 256>>>(x, h);
    uv_kernel<<<N_NODES, 256>>>(We0, be0);
    edge_kernel<<<dim3(JT, N_NODES / 2), 256, EDGE_SMEM_BYTES>>>(
        x, We0, be1, Winf, binf, bx0, bx1, Wxo, bxo);
    hnode_kernel<<<N_NODES, 256>>>(h, Wh0, bh0, Wh1, bh1, Who, bho, out);
    xout_kernel<<<48, 256>>>(x, out);
}

// round 7
// speedup vs baseline: 7.2952x; 1.3429x over previous
#include <cuda_runtime.h>
#include <cuda_fp16.h>
#include <cstdint>

#define N_NODES 512
#define HD      128
#define FD      192
#define MD      256
#define JT      8
#define TJ      64
#define SA_STRH 264      // sA row stride in halves (132 words == 4 mod 32)
#define STG_STRH 72      // stage row stride in halves (36 words == 4 mod 32)

// ---------------- device scratch ----------------
__device__ float g_hc[N_NODES * FD];
__device__ float g_u [N_NODES * MD];
__device__ float g_v [N_NODES * MD];
__device__ float g_mi_part   [JT * N_NODES * MD];
__device__ float g_shift_part[JT * N_NODES * 24];
__device__ __half g_We1h[MD * MD];   // Wt[n][k] = half(W[k][n])
__device__ __half g_Wx0h[MD * MD];
__device__ __half g_Wx1h[MD * MD];

__device__ __forceinline__ float silu_f(float v) { return v / (1.f + __expf(-v)); }

__device__ __forceinline__ uint32_t smem_u32(const void* p) {
    uint32_t a;
    asm("{ .reg .u64 t; cvta.to.shared.u64 t, %1; cvt.u32.u64 %0, t; }" : "=r"(a) : "l"(p));
    return a;
}

__device__ __forceinline__ void mma_fp16(float* d, uint32_t a0, uint32_t a1,
                                         uint32_t a2, uint32_t a3,
                                         uint32_t b0, uint32_t b1) {
    asm volatile("mma.sync.aligned.m16n8k16.row.col.f32.f16.f16.f32 "
                 "{%0,%1,%2,%3}, {%4,%5,%6,%7}, {%8,%9}, {%0,%1,%2,%3};\n"
                 : "+f"(d[0]), "+f"(d[1]), "+f"(d[2]), "+f"(d[3])
                 : "r"(a0), "r"(a1), "r"(a2), "r"(a3), "r"(b0), "r"(b1));
}

// ---------------- smem layout (byte offsets, 128-aligned) ----------------
#define SA_OFF    0         // 67584 : A/C tile [128][264] half
#define ST0_OFF   67584     // 36864 : stage buf 0 [256][72] half
#define ST1_OFF   104448    // 36864 : stage buf 1
#define AUX_OFF   141312    // 8192  : We0 rows 0..7 fp32, later Wxo fp32
#define SQN_OFF   149504    // 4096  : sqn [2][64][8] fp32
#define XSJ_OFF   153600    // 6144  : x_j [64][24]
#define XSI_OFF   159744    // 192   : x_i [2][24]
#define WINF_OFF  159936    // 1024
#define RED_OFF   160960    // 512   : gate partials [128]
#define ES_OFF    161472    // 512   : e [128]
#define PXP_OFF   161984    // 16384 : px partials [4][128][8]
#define EDGE_SMEM_BYTES (178368 + 128)

// ---------------- K0: transpose + halve weights ----------------
__global__ void prep_kernel(const float* __restrict__ We1, const float* __restrict__ Wx0,
                            const float* __restrict__ Wx1) {
    __shared__ float t[32][33];
    int b = blockIdx.x;            // 192 blocks
    int mat = b >> 6, tile = b & 63;
    int tk = tile >> 3, tn = tile & 7;
    const float* S = (mat == 0) ? We1 : (mat == 1) ? Wx0 : Wx1;
    __half* D = (mat == 0) ? g_We1h : (mat == 1) ? g_Wx0h : g_Wx1h;
    int r0 = threadIdx.x >> 5, c = threadIdx.x & 31;
#pragma unroll
    for (int q = 0; q < 4; q++) {
        int r = r0 + q * 8;
        t[r][c] = S[(tk * 32 + r) * 256 + tn * 32 + c];
    }
    __syncthreads();
#pragma unroll
    for (int q = 0; q < 4; q++) {
        int r = r0 + q * 8;
        D[(tn * 32 + r) * 256 + tk * 32 + c] = __float2half_rn(t[c][r]);
    }
}

// ---------------- K1: hc ----------------
__global__ void hc_kernel(const float* __restrict__ x, const float* __restrict__ h) {
    int n = blockIdx.x, t = threadIdx.x;
    __shared__ float xi[24];
    if (t < 24) xi[t] = x[n * 24 + t];
    __syncthreads();
    if (t < HD) {
        g_hc[n * FD + t] = h[n * HD + t];
    } else if (t < FD) {
        int p = t - HD; int a = p >> 3, b = p & 7;
        float s = 0.f;
#pragma unroll
        for (int d = 0; d < 3; d++) { float dd = xi[a*3+d] - xi[b*3+d]; s += dd * dd; }
        g_hc[n * FD + t] = s;
    }
}

// ---------------- K2: u, v ----------------
__global__ void uv_kernel(const float* __restrict__ We0, const float* __restrict__ be0) {
    int n = blockIdx.x, t = threadIdx.x;
    __shared__ float hcs[FD];
    if (t < FD) hcs[t] = g_hc[n * FD + t];
    __syncthreads();
    float su = 0.f, sv = 0.f;
#pragma unroll 4
    for (int k = 0; k < FD; k++) {
        float hv = hcs[k];
        su += hv * We0[(8   + k) * MD + t];
        sv += hv * We0[(200 + k) * MD + t];
    }
    g_u[n * MD + t] = su;
    g_v[n * MD + t] = sv + be0[t];
}

// ---------------- weight staging: 64 k-halves for all 256 n ----------------
__device__ __forceinline__ void stage_cp64(const __half* __restrict__ Wt, int kc,
                                           uint32_t dst, int tid) {
#pragma unroll
    for (int p = 0; p < 4; p++) {
        int s = tid + p * 512;                 // 2048 jobs of 16B
        int n = s >> 3, q = s & 7;
        const __half* src = Wt + n * 256 + kc * 64 + q * 8;
        uint32_t d = dst + (uint32_t)(n * (STG_STRH * 2) + q * 16);
        asm volatile("cp.async.cg.shared.global [%0], [%1], 16;" :: "r"(d), "l"(src));
    }
}

// ---------------- fp16 tensor GEMM: acc = sA[128x256] @ Wt^T ----------------
// 16 warps, warp tile 32 rows x 64 cols: wr=w&3 row group, wc=w>>2 col group
__device__ __forceinline__ void gemm_fp16(const __half* __restrict__ sA,
                                          const __half* __restrict__ stp0,
                                          const __half* __restrict__ stp1,
                                          uint32_t st0, uint32_t st1,
                                          const __half* __restrict__ Wt,
                                          float acc[2][8][4], int tid) {
    int lane = tid & 31, w = tid >> 5;
    int wr = w & 3, wc = w >> 2;
    int g = lane >> 2, t4 = lane & 3;
#pragma unroll
    for (int mt = 0; mt < 2; mt++)
#pragma unroll
        for (int nt = 0; nt < 8; nt++)
#pragma unroll
            for (int e = 0; e < 4; e++) acc[mt][nt][e] = 0.f;

    stage_cp64(Wt, 0, st0, tid);
    asm volatile("cp.async.commit_group;" ::: "memory");
#pragma unroll 1
    for (int s = 0; s < 4; s++) {
        if (s < 3) {
            stage_cp64(Wt, s + 1, (s & 1) ? st0 : st1, tid);
            asm volatile("cp.async.commit_group;" ::: "memory");
            asm volatile("cp.async.wait_group 1;" ::: "memory");
        } else {
            asm volatile("cp.async.wait_group 0;" ::: "memory");
        }
        __syncthreads();
        const __half* stg = (s & 1) ? stp1 : stp0;
#pragma unroll
        for (int ks = 0; ks < 4; ks++) {
            uint32_t b0[8], b1[8];
#pragma unroll
            for (int nt = 0; nt < 8; nt++) {
                int nc = wc * 64 + nt * 8 + g;
                const uint32_t* bp = (const uint32_t*)(stg + nc * STG_STRH + ks * 16 + 2 * t4);
                b0[nt] = bp[0];
                b1[nt] = bp[4];
            }
            int kw = s * 64 + ks * 16 + 2 * t4;
#pragma unroll
            for (int mt = 0; mt < 2; mt++) {
                int row = wr * 32 + mt * 16 + g;
                const uint32_t* ap0 = (const uint32_t*)(sA + row * SA_STRH + kw);
                const uint32_t* ap1 = (const uint32_t*)(sA + (row + 8) * SA_STRH + kw);
                uint32_t a0 = ap0[0], a2 = ap0[4];
                uint32_t a1 = ap1[0], a3 = ap1[4];
#pragma unroll
                for (int nt = 0; nt < 8; nt++)
                    mma_fp16(acc[mt][nt], a0, a1, a2, a3, b0[nt], b1[nt]);
            }
        }
        __syncthreads();     // protect stage buffer before next overwrite / sA epilogue
    }
}

// ---------------- K3: fused edge pipeline ----------------
__global__ __launch_bounds__(512, 1)
void edge_kernel(const float* __restrict__ x,
                 const float* __restrict__ We0,
                 const float* __restrict__ be1,
                 const float* __restrict__ Winf, const float* __restrict__ binf,
                 const float* __restrict__ bx0, const float* __restrict__ bx1,
                 const float* __restrict__ Wxo, const float* __restrict__ bxo) {
    extern __shared__ __align__(128) char smem[];
    __half* sA    = (__half*)(smem + SA_OFF);
    __half* stp0  = (__half*)(smem + ST0_OFF);
    __half* stp1  = (__half*)(smem + ST1_OFF);
    float* sAux  = (float*)(smem + AUX_OFF);
    float* sqn_s = (float*)(smem + SQN_OFF);
    float* xs_j  = (float*)(smem + XSJ_OFF);
    float* xs_i  = (float*)(smem + XSI_OFF);
    float* sWinf = (float*)(smem + WINF_OFF);
    float* red   = (float*)(smem + RED_OFF);
    float* e_s   = (float*)(smem + ES_OFF);
    float* pxp   = (float*)(smem + PXP_OFF);
    uint32_t sbase = smem_u32(smem);
    uint32_t st0 = sbase + ST0_OFF, st1 = sbase + ST1_OFF;

    int tid = threadIdx.x;
    int lane = tid & 31, w = tid >> 5;
    int wr = w & 3, wc = w >> 2;
    int g = lane >> 2, t4 = lane & 3;
    int jt = blockIdx.x, ip = blockIdx.y;
    int i0 = ip * 2, i1 = i0 + 1, j0 = jt * TJ;

    // --- stage geometry + constants ---
    if (tid < 256) sWinf[tid] = Winf[tid];
    for (int q = tid; q < 8 * MD; q += 512) sAux[q] = We0[q];
    if (tid < 48) xs_i[tid] = x[i0 * 24 + tid];
    for (int q = tid; q < TJ * 24; q += 512) xs_j[q] = x[j0 * 24 + q];
    if (tid < 128) red[tid] = 0.f;
    __syncthreads();

    for (int q = tid; q < 2 * TJ * 8; q += 512) {
        int half = q >> 9, rem = q & 511, jl = rem >> 3, hh = rem & 7;
        float s = 0.f;
#pragma unroll
        for (int d = 0; d < 3; d++) {
            float dd = xs_j[jl*24 + hh*3 + d] - xs_i[half*24 + hh*3 + d];
            s += dd * dd;
        }
        sqn_s[q] = s;
    }
    __syncthreads();

    // --- A1 = half(silu(sqn @ We0[0:8] + u[j] + v[i])) ---
    {
        int c = tid & 255, hs = tid >> 8;      // hs: which i (row half)
        float vv = g_v[(hs ? i1 : i0) * MD + c];
        float w8[8];
#pragma unroll
        for (int t8 = 0; t8 < 8; t8++) w8[t8] = sAux[t8 * 256 + c];
        for (int jl = 0; jl < TJ; jl++) {
            int r = hs * 64 + jl;
            float a = vv + g_u[(j0 + jl) * MD + c];
#pragma unroll
            for (int t8 = 0; t8 < 8; t8++) a += sqn_s[hs * 512 + jl * 8 + t8] * w8[t8];
            sA[r * SA_STRH + c] = __float2half_rn(silu_f(a));
        }
    }
    __syncthreads();
    // restage sAux with Wxo for the px phase
    for (int q = tid; q < 2048; q += 512) sAux[q] = Wxo[q];

    float acc[2][8][4];

    // ================= GEMM1: m = silu(A1 @ We1 + be1), masked =================
    gemm_fp16(sA, stp0, stp1, st0, st1, g_We1h, acc, tid);
    {
#pragma unroll
        for (int mt = 0; mt < 2; mt++) {
            int r0 = wr * 32 + mt * 16 + g, r1 = r0 + 8;
            bool s0 = (j0 + (r0 & 63)) == ((r0 < 64) ? i0 : i1);
            bool s1 = (j0 + (r1 & 63)) == ((r1 < 64) ? i0 : i1);
            float gp0 = 0.f, gp1 = 0.f;
#pragma unroll
            for (int nt = 0; nt < 8; nt++) {
                int cn = wc * 64 + nt * 8 + 2 * t4;
                float w0 = sWinf[cn], w1 = sWinf[cn + 1];
                float b0v = be1[cn], b1v = be1[cn + 1];
                float v0 = s0 ? 0.f : silu_f(acc[mt][nt][0] + b0v);
                float v1 = s0 ? 0.f : silu_f(acc[mt][nt][1] + b1v);
                float v2 = s1 ? 0.f : silu_f(acc[mt][nt][2] + b0v);
                float v3 = s1 ? 0.f : silu_f(acc[mt][nt][3] + b1v);
                *(__half2*)&sA[r0 * SA_STRH + cn] = __floats2half2_rn(v0, v1);
                *(__half2*)&sA[r1 * SA_STRH + cn] = __floats2half2_rn(v2, v3);
                gp0 += v0 * w0 + v1 * w1;
                gp1 += v2 * w0 + v3 * w1;
            }
            gp0 += __shfl_xor_sync(0xffffffff, gp0, 1);
            gp0 += __shfl_xor_sync(0xffffffff, gp0, 2);
            gp1 += __shfl_xor_sync(0xffffffff, gp1, 1);
            gp1 += __shfl_xor_sync(0xffffffff, gp1, 2);
            if (t4 == 0) { atomicAdd(&red[r0], gp0); atomicAdd(&red[r1], gp1); }
        }
    }
    __syncthreads();

    // --- gate e ---
    if (tid < 128) {
        float s = red[tid] + binf[0];
        int jj = j0 + (tid & 63), ii = (tid < 64) ? i0 : i1;
        e_s[tid] = (jj == ii) ? 0.f : 1.f / (1.f + __expf(-s));
    }
    __syncthreads();

    // --- m_i partials ---
    {
        int c = tid & 255, half = tid >> 8;
        float a = 0.f;
        int rb = half * 64;
#pragma unroll 4
        for (int rr = 0; rr < 64; rr++)
            a += __half2float(sA[(rb + rr) * SA_STRH + c]) * e_s[rb + rr];
        g_mi_part[(jt * N_NODES + (half ? i1 : i0)) * MD + c] = a;
    }
    __syncthreads();

    // ================= GEMM2: s1 = silu(m @ Wx0 + bx0) =================
    gemm_fp16(sA, stp0, stp1, st0, st1, g_Wx0h, acc, tid);
#pragma unroll
    for (int mt = 0; mt < 2; mt++) {
        int r0 = wr * 32 + mt * 16 + g, r1 = r0 + 8;
#pragma unroll
        for (int nt = 0; nt < 8; nt++) {
            int cn = wc * 64 + nt * 8 + 2 * t4;
            float b0v = bx0[cn], b1v = bx0[cn + 1];
            *(__half2*)&sA[r0 * SA_STRH + cn] =
                __floats2half2_rn(silu_f(acc[mt][nt][0] + b0v), silu_f(acc[mt][nt][1] + b1v));
            *(__half2*)&sA[r1 * SA_STRH + cn] =
                __floats2half2_rn(silu_f(acc[mt][nt][2] + b0v), silu_f(acc[mt][nt][3] + b1v));
        }
    }
    __syncthreads();

    // ================= GEMM3: s2 = silu(s1 @ Wx1 + bx1) =================
    gemm_fp16(sA, stp0, stp1, st0, st1, g_Wx1h, acc, tid);
#pragma unroll
    for (int mt = 0; mt < 2; mt++) {
        int r0 = wr * 32 + mt * 16 + g, r1 = r0 + 8;
#pragma unroll
        for (int nt = 0; nt < 8; nt++) {
            int cn = wc * 64 + nt * 8 + 2 * t4;
            float b0v = bx1[cn], b1v = bx1[cn + 1];
            *(__half2*)&sA[r0 * SA_STRH + cn] =
                __floats2half2_rn(silu_f(acc[mt][nt][0] + b0v), silu_f(acc[mt][nt][1] + b1v));
            *(__half2*)&sA[r1 * SA_STRH + cn] =
                __floats2half2_rn(silu_f(acc[mt][nt][2] + b0v), silu_f(acc[mt][nt][3] + b1v));
        }
    }
    __syncthreads();

    // --- px partials: px[r] = s2[r] @ Wxo (4 column chunks) ---
    {
        int r = tid & 127, chunk = tid >> 7;
        float pa[8];
#pragma unroll
        for (int hh = 0; hh < 8; hh++) pa[hh] = 0.f;
        int c0 = chunk * 64;
        for (int c = c0; c < c0 + 64; c++) {
            float v = __half2float(sA[r * SA_STRH + c]);
#pragma unroll
            for (int hh = 0; hh < 8; hh++) pa[hh] += v * sAux[c * 8 + hh];
        }
#pragma unroll
        for (int hh = 0; hh < 8; hh++) pxp[(chunk * 128 + r) * 8 + hh] = pa[hh];
    }
    __syncthreads();
    if (tid < 128) {
#pragma unroll
        for (int hh = 0; hh < 8; hh++)
            pxp[tid * 8 + hh] = pxp[tid * 8 + hh] + pxp[(128 + tid) * 8 + hh]
                              + pxp[(256 + tid) * 8 + hh] + pxp[(384 + tid) * 8 + hh] + bxo[hh];
    }
    __syncthreads();

    // --- shift partials ---
    if (tid < 48) {
        int half = tid / 24, q = tid % 24, hh = q / 3, d = q % 3;
        int ii = half ? i1 : i0;
        float accs = 0.f;
        for (int jl = 0; jl < TJ; jl++) {
            float dn  = xs_j[jl*24 + hh*3 + d] - xs_i[half*24 + hh*3 + d];
            float nrm = sqrtf(sqn_s[half*512 + jl*8 + hh] + 1e-8f) + 1.0f;
            accs += (dn / nrm) * pxp[(half * 64 + jl) * 8 + hh];
        }
        g_shift_part[(jt * N_NODES + ii) * 24 + q] = accs;
    }
}

// ---------------- K4: phi_h per node ----------------
__global__ void hnode_kernel(const float* __restrict__ h,
                             const float* __restrict__ Wh0, const float* __restrict__ bh0,
                             const float* __restrict__ Wh1, const float* __restrict__ bh1,
                             const float* __restrict__ Who, const float* __restrict__ bho,
                             float* __restrict__ out) {
    int n = blockIdx.x, t = threadIdx.x;
    __shared__ float sin_s[384];
    __shared__ float s1[256];
    __shared__ float s2[256];
    float mi = 0.f;
#pragma unroll
    for (int p = 0; p < JT; p++) mi += g_mi_part[(p * N_NODES + n) * MD + t];
    sin_s[t] = mi;
    if (t < HD) sin_s[256 + t] = h[n * HD + t];
    __syncthreads();
    {
        float a0=0,a1=0,a2=0,a3=0;
        for (int k = 0; k < 384; k += 4) {
            a0 += sin_s[k  ] * Wh0[(k  ) * 256 + t];
            a1 += sin_s[k+1] * Wh0[(k+1) * 256 + t];
            a2 += sin_s[k+2] * Wh0[(k+2) * 256 + t];
            a3 += sin_s[k+3] * Wh0[(k+3) * 256 + t];
        }
        s1[t] = silu_f(a0 + a1 + a2 + a3 + bh0[t]);
    }
    __syncthreads();
    {
        float a0=0,a1=0,a2=0,a3=0;
        for (int k = 0; k < 256; k += 4) {
            a0 += s1[k  ] * Wh1[(k  ) * 256 + t];
            a1 += s1[k+1] * Wh1[(k+1) * 256 + t];
            a2 += s1[k+2] * Wh1[(k+2) * 256 + t];
            a3 += s1[k+3] * Wh1[(k+3) * 256 + t];
        }
        s2[t] = silu_f(a0 + a1 + a2 + a3 + bh1[t]);
    }
    __syncthreads();
    if (t < HD) {
        float a0=0,a1=0,a2=0,a3=0;
        for (int k = 0; k < 256; k += 4) {
            a0 += s2[k  ] * Who[(k  ) * 128 + t];
            a1 += s2[k+1] * Who[(k+1) * 128 + t];
            a2 += s2[k+2] * Who[(k+2) * 128 + t];
            a3 += s2[k+3] * Who[(k+3) * 128 + t];
        }
        out[12288 + n * HD + t] = h[n * HD + t] + a0 + a1 + a2 + a3 + bho[t];
    }
}

// ---------------- K5: x_new ----------------
__global__ void xout_kernel(const float* __restrict__ x, float* __restrict__ out) {
    int idx = blockIdx.x * blockDim.x + threadIdx.x;
    if (idx < N_NODES * 24) {
        float s = 0.f;
#pragma unroll
        for (int p = 0; p < JT; p++) s += g_shift_part[p * N_NODES * 24 + idx];
        out[idx] = x[idx] + s / (float)(N_NODES - 1);
    }
}

// ---------------- launch ----------------
extern "C" void kernel_launch(void* const* d_in, const int* in_sizes, int n_in,
                              void* d_out, int out_size) {
    const float* x    = (const float*)d_in[0];
    const float* h    = (const float*)d_in[1];
    const float* We0  = (const float*)d_in[2];
    const float* be0  = (const float*)d_in[3];
    const float* We1  = (const float*)d_in[4];
    const float* be1  = (const float*)d_in[5];
    const float* Winf = (const float*)d_in[6];
    const float* binf = (const float*)d_in[7];
    const float* Wx0  = (const float*)d_in[8];
    const float* bx0  = (const float*)d_in[9];
    const float* Wx1  = (const float*)d_in[10];
    const float* bx1  = (const float*)d_in[11];
    const float* Wxo  = (const float*)d_in[12];
    const float* bxo  = (const float*)d_in[13];
    const float* Wh0  = (const float*)d_in[14];
    const float* bh0  = (const float*)d_in[15];
    const float* Wh1  = (const float*)d_in[16];
    const float* bh1  = (const float*)d_in[17];
    const float* Who  = (const float*)d_in[18];
    const float* bho  = (const float*)d_in[19];
    float* out = (float*)d_out;

    cudaFuncSetAttribute(edge_kernel, cudaFuncAttributeMaxDynamicSharedMemorySize,
                         EDGE_SMEM_BYTES);

    prep_kernel<<<192, 256>>>(We1, Wx0, Wx1);
    hc_kernel<<<N_NODES, 256>>>(x, h);
    uv_kernel<<<N_NODES, 256>>>(We0, be0);
    edge_kernel<<<dim3(JT, N_NODES / 2), 512, EDGE_SMEM_BYTES>>>(
        x, We0, be1, Winf, binf, bx0, bx1, Wxo, bxo);
    hnode_kernel<<<N_NODES, 256>>>(h, Wh0, bh0, Wh1, bh1, Who, bho, out);
    xout_kernel<<<48, 256>>>(x, out);
}

// round 8
// speedup vs baseline: 7.4796x; 1.0253x over previous
#include <cuda_runtime.h>
#include <cuda_fp16.h>
#include <cstdint>

#define N_NODES 512
#define HD      128
#define FD      192
#define MD      256
#define JT      8
#define TJ      64
#define SA_STRH 264      // sA row stride in halves (132 words == 4 mod 32)
#define SW_STRH 264      // weight row stride in halves (same property)

// ---------------- device scratch ----------------
__device__ float g_hc[N_NODES * FD];
__device__ float g_u [N_NODES * MD];
__device__ float g_v [N_NODES * MD];
__device__ float g_mi_part   [JT * N_NODES * MD];
__device__ float g_shift_part[JT * N_NODES * 24];
__device__ __half g_We1h[MD * MD];   // Wt[n][k] = half(W[k][n])
__device__ __half g_Wx0h[MD * MD];
__device__ __half g_Wx1h[MD * MD];

__device__ __forceinline__ float silu_f(float v) { return v / (1.f + __expf(-v)); }

__device__ __forceinline__ uint32_t smem_u32(const void* p) {
    uint32_t a;
    asm("{ .reg .u64 t; cvta.to.shared.u64 t, %1; cvt.u32.u64 %0, t; }" : "=r"(a) : "l"(p));
    return a;
}

__device__ __forceinline__ void mma_fp16(float* d, uint32_t a0, uint32_t a1,
                                         uint32_t a2, uint32_t a3,
                                         uint32_t b0, uint32_t b1) {
    asm volatile("mma.sync.aligned.m16n8k16.row.col.f32.f16.f16.f32 "
                 "{%0,%1,%2,%3}, {%4,%5,%6,%7}, {%8,%9}, {%0,%1,%2,%3};\n"
                 : "+f"(d[0]), "+f"(d[1]), "+f"(d[2]), "+f"(d[3])
                 : "r"(a0), "r"(a1), "r"(a2), "r"(a3), "r"(b0), "r"(b1));
}

// ---------------- smem layout (byte offsets, 128-aligned) ----------------
#define SA_OFF    0         // 67584  : A/C tile [128][264] half
#define SW_OFF    67584     // 135168 : FULL weight matrix [256][264] half
#define PXP_OFF   SW_OFF    // overlay: px partials [4][128][8] f32 (16KB, after GEMM3)
#define AUX_OFF   202752    // 8192   : We0 rows 0..7 fp32, later Wxo fp32
#define SQN_OFF   210944    // 4096   : sqn [2][64][8] fp32
#define XSJ_OFF   215040    // 6144   : x_j [64][24]
#define XSI_OFF   221184    // 192    : x_i [2][24]
#define WINF_OFF  221376    // 1024
#define RED_OFF   222400    // 512    : gate partials [128]
#define ES_OFF    222912    // 512    : e [128]
#define EDGE_SMEM_BYTES (223424 + 128)

// ---------------- K0: transpose + halve weights ----------------
__global__ void prep_kernel(const float* __restrict__ We1, const float* __restrict__ Wx0,
                            const float* __restrict__ Wx1) {
    __shared__ float t[32][33];
    int b = blockIdx.x;            // 192 blocks
    int mat = b >> 6, tile = b & 63;
    int tk = tile >> 3, tn = tile & 7;
    const float* S = (mat == 0) ? We1 : (mat == 1) ? Wx0 : Wx1;
    __half* D = (mat == 0) ? g_We1h : (mat == 1) ? g_Wx0h : g_Wx1h;
    int r0 = threadIdx.x >> 5, c = threadIdx.x & 31;
#pragma unroll
    for (int q = 0; q < 4; q++) {
        int r = r0 + q * 8;
        t[r][c] = S[(tk * 32 + r) * 256 + tn * 32 + c];
    }
    __syncthreads();
#pragma unroll
    for (int q = 0; q < 4; q++) {
        int r = r0 + q * 8;
        D[(tn * 32 + r) * 256 + tk * 32 + c] = __float2half_rn(t[c][r]);
    }
}

// ---------------- K1: hc ----------------
__global__ void hc_kernel(const float* __restrict__ x, const float* __restrict__ h) {
    int n = blockIdx.x, t = threadIdx.x;
    __shared__ float xi[24];
    if (t < 24) xi[t] = x[n * 24 + t];
    __syncthreads();
    if (t < HD) {
        g_hc[n * FD + t] = h[n * HD + t];
    } else if (t < FD) {
        int p = t - HD; int a = p >> 3, b = p & 7;
        float s = 0.f;
#pragma unroll
        for (int d = 0; d < 3; d++) { float dd = xi[a*3+d] - xi[b*3+d]; s += dd * dd; }
        g_hc[n * FD + t] = s;
    }
}

// ---------------- K2: u, v ----------------
__global__ void uv_kernel(const float* __restrict__ We0, const float* __restrict__ be0) {
    int n = blockIdx.x, t = threadIdx.x;
    __shared__ float hcs[FD];
    if (t < FD) hcs[t] = g_hc[n * FD + t];
    __syncthreads();
    float su = 0.f, sv = 0.f;
#pragma unroll 4
    for (int k = 0; k < FD; k++) {
        float hv = hcs[k];
        su += hv * We0[(8   + k) * MD + t];
        sv += hv * We0[(200 + k) * MD + t];
    }
    g_u[n * MD + t] = su;
    g_v[n * MD + t] = sv + be0[t];
}

// ---------------- full-weight cp.async load: 256x256 halves ----------------
__device__ __forceinline__ void cp_full(const __half* __restrict__ Wt, uint32_t dst, int tid) {
#pragma unroll
    for (int p = 0; p < 16; p++) {
        int s = tid + p * 512;                 // 8192 jobs of 16B
        int n = s >> 5, q = s & 31;
        const __half* src = Wt + n * 256 + q * 8;
        uint32_t d = dst + (uint32_t)(n * (SW_STRH * 2) + q * 16);
        asm volatile("cp.async.cg.shared.global [%0], [%1], 16;" :: "r"(d), "l"(src));
    }
    asm volatile("cp.async.commit_group;" ::: "memory");
}

// ---------------- barrier-free fp16 tensor GEMM over full K=256 ----------------
// 16 warps, warp tile 32 rows x 64 cols: wr=w&3, wc=w>>2
__device__ __forceinline__ void gemm_full(const __half* __restrict__ sA,
                                          const __half* __restrict__ sW,
                                          float acc[2][8][4], int tid) {
    int lane = tid & 31, w = tid >> 5;
    int wr = w & 3, wc = w >> 2;
    int g = lane >> 2, t4 = lane & 3;
#pragma unroll
    for (int mt = 0; mt < 2; mt++)
#pragma unroll
        for (int nt = 0; nt < 8; nt++)
#pragma unroll
            for (int e = 0; e < 4; e++) acc[mt][nt][e] = 0.f;

#pragma unroll 2
    for (int ks = 0; ks < 16; ks++) {
        int kw = ks * 16 + 2 * t4;
        uint32_t b0[8], b1[8];
#pragma unroll
        for (int nt = 0; nt < 8; nt++) {
            int nc = wc * 64 + nt * 8 + g;
            const uint32_t* bp = (const uint32_t*)(sW + nc * SW_STRH + kw);
            b0[nt] = bp[0];
            b1[nt] = bp[4];
        }
#pragma unroll
        for (int mt = 0; mt < 2; mt++) {
            int row = wr * 32 + mt * 16 + g;
            const uint32_t* ap0 = (const uint32_t*)(sA + row * SA_STRH + kw);
            const uint32_t* ap1 = (const uint32_t*)(sA + (row + 8) * SA_STRH + kw);
            uint32_t a0 = ap0[0], a2 = ap0[4];
            uint32_t a1 = ap1[0], a3 = ap1[4];
#pragma unroll
            for (int nt = 0; nt < 8; nt++)
                mma_fp16(acc[mt][nt], a0, a1, a2, a3, b0[nt], b1[nt]);
        }
    }
}

// ---------------- K3: fused edge pipeline ----------------
__global__ __launch_bounds__(512, 1)
void edge_kernel(const float* __restrict__ x,
                 const float* __restrict__ We0,
                 const float* __restrict__ be1,
                 const float* __restrict__ Winf, const float* __restrict__ binf,
                 const float* __restrict__ bx0, const float* __restrict__ bx1,
                 const float* __restrict__ Wxo, const float* __restrict__ bxo) {
    extern __shared__ __align__(128) char smem[];
    __half* sA    = (__half*)(smem + SA_OFF);
    __half* sW    = (__half*)(smem + SW_OFF);
    float* pxp   = (float*)(smem + PXP_OFF);
    float* sAux  = (float*)(smem + AUX_OFF);
    float* sqn_s = (float*)(smem + SQN_OFF);
    float* xs_j  = (float*)(smem + XSJ_OFF);
    float* xs_i  = (float*)(smem + XSI_OFF);
    float* sWinf = (float*)(smem + WINF_OFF);
    float* red   = (float*)(smem + RED_OFF);
    float* e_s   = (float*)(smem + ES_OFF);
    uint32_t sbase = smem_u32(smem);
    uint32_t swa = sbase + SW_OFF;

    int tid = threadIdx.x;
    int lane = tid & 31, w = tid >> 5;
    int wr = w & 3, wc = w >> 2;
    int g = lane >> 2, t4 = lane & 3;
    int jt = blockIdx.x, ip = blockIdx.y;
    int i0 = ip * 2, i1 = i0 + 1, j0 = jt * TJ;

    // kick off GEMM1 weight load immediately — overlaps all the prologue work
    cp_full(g_We1h, swa, tid);

    // --- stage geometry + constants ---
    if (tid < 256) sWinf[tid] = Winf[tid];
    for (int q = tid; q < 8 * MD; q += 512) sAux[q] = We0[q];
    if (tid < 48) xs_i[tid] = x[i0 * 24 + tid];
    for (int q = tid; q < TJ * 24; q += 512) xs_j[q] = x[j0 * 24 + q];
    if (tid < 128) red[tid] = 0.f;
    __syncthreads();

    for (int q = tid; q < 2 * TJ * 8; q += 512) {
        int half = q >> 9, rem = q & 511, jl = rem >> 3, hh = rem & 7;
        float s = 0.f;
#pragma unroll
        for (int d = 0; d < 3; d++) {
            float dd = xs_j[jl*24 + hh*3 + d] - xs_i[half*24 + hh*3 + d];
            s += dd * dd;
        }
        sqn_s[q] = s;
    }
    __syncthreads();

    // --- A1 = half(silu(sqn @ We0[0:8] + u[j] + v[i])) ---
    {
        int c = tid & 255, hs = tid >> 8;
        float vv = g_v[(hs ? i1 : i0) * MD + c];
        float w8[8];
#pragma unroll
        for (int t8 = 0; t8 < 8; t8++) w8[t8] = sAux[t8 * 256 + c];
        for (int jl = 0; jl < TJ; jl++) {
            int r = hs * 64 + jl;
            float a = vv + g_u[(j0 + jl) * MD + c];
#pragma unroll
            for (int t8 = 0; t8 < 8; t8++) a += sqn_s[hs * 512 + jl * 8 + t8] * w8[t8];
            sA[r * SA_STRH + c] = __float2half_rn(silu_f(a));
        }
    }
    asm volatile("cp.async.wait_group 0;" ::: "memory");
    __syncthreads();     // A1 + We1 both ready

    float acc[2][8][4];

    // ================= GEMM1 (barrier-free) =================
    gemm_full(sA, sW, acc, tid);
    __syncthreads();                       // all sA/sW readers done
    cp_full(g_Wx0h, swa, tid);             // next weights load under epilogue

    // --- epilogue 1: m = mask(silu(.+be1)); gate partials; write sA ---
    {
#pragma unroll
        for (int mt = 0; mt < 2; mt++) {
            int r0 = wr * 32 + mt * 16 + g, r1 = r0 + 8;
            bool s0 = (j0 + (r0 & 63)) == ((r0 < 64) ? i0 : i1);
            bool s1 = (j0 + (r1 & 63)) == ((r1 < 64) ? i0 : i1);
            float gp0 = 0.f, gp1 = 0.f;
#pragma unroll
            for (int nt = 0; nt < 8; nt++) {
                int cn = wc * 64 + nt * 8 + 2 * t4;
                float w0 = sWinf[cn], w1 = sWinf[cn + 1];
                float b0v = be1[cn], b1v = be1[cn + 1];
                float v0 = s0 ? 0.f : silu_f(acc[mt][nt][0] + b0v);
                float v1 = s0 ? 0.f : silu_f(acc[mt][nt][1] + b1v);
                float v2 = s1 ? 0.f : silu_f(acc[mt][nt][2] + b0v);
                float v3 = s1 ? 0.f : silu_f(acc[mt][nt][3] + b1v);
                *(__half2*)&sA[r0 * SA_STRH + cn] = __floats2half2_rn(v0, v1);
                *(__half2*)&sA[r1 * SA_STRH + cn] = __floats2half2_rn(v2, v3);
                gp0 += v0 * w0 + v1 * w1;
                gp1 += v2 * w0 + v3 * w1;
            }
            gp0 += __shfl_xor_sync(0xffffffff, gp0, 1);
            gp0 += __shfl_xor_sync(0xffffffff, gp0, 2);
            gp1 += __shfl_xor_sync(0xffffffff, gp1, 1);
            gp1 += __shfl_xor_sync(0xffffffff, gp1, 2);
            if (t4 == 0) { atomicAdd(&red[r0], gp0); atomicAdd(&red[r1], gp1); }
        }
    }
    __syncthreads();

    // --- gate e ---
    if (tid < 128) {
        float s = red[tid] + binf[0];
        int jj = j0 + (tid & 63), ii = (tid < 64) ? i0 : i1;
        e_s[tid] = (jj == ii) ? 0.f : 1.f / (1.f + __expf(-s));
    }
    __syncthreads();

    // --- m_i partials ---
    {
        int c = tid & 255, half = tid >> 8;
        float a = 0.f;
        int rb = half * 64;
#pragma unroll 4
        for (int rr = 0; rr < 64; rr++)
            a += __half2float(sA[(rb + rr) * SA_STRH + c]) * e_s[rb + rr];
        g_mi_part[(jt * N_NODES + (half ? i1 : i0)) * MD + c] = a;
    }
    asm volatile("cp.async.wait_group 0;" ::: "memory");
    __syncthreads();     // Wx0 ready

    // ================= GEMM2 =================
    gemm_full(sA, sW, acc, tid);
    __syncthreads();
    cp_full(g_Wx1h, swa, tid);             // Wx1 load under epilogue
#pragma unroll
    for (int mt = 0; mt < 2; mt++) {
        int r0 = wr * 32 + mt * 16 + g, r1 = r0 + 8;
#pragma unroll
        for (int nt = 0; nt < 8; nt++) {
            int cn = wc * 64 + nt * 8 + 2 * t4;
            float b0v = bx0[cn], b1v = bx0[cn + 1];
            *(__half2*)&sA[r0 * SA_STRH + cn] =
                __floats2half2_rn(silu_f(acc[mt][nt][0] + b0v), silu_f(acc[mt][nt][1] + b1v));
            *(__half2*)&sA[r1 * SA_STRH + cn] =
                __floats2half2_rn(silu_f(acc[mt][nt][2] + b0v), silu_f(acc[mt][nt][3] + b1v));
        }
    }
    asm volatile("cp.async.wait_group 0;" ::: "memory");
    __syncthreads();     // sA(s1) + Wx1 ready

    // ================= GEMM3 =================
    gemm_full(sA, sW, acc, tid);
    __syncthreads();     // sW readers done (pxp overlay becomes safe)

    // --- epilogue 3: s2 -> sA; Wxo -> sAux ---
#pragma unroll
    for (int mt = 0; mt < 2; mt++) {
        int r0 = wr * 32 + mt * 16 + g, r1 = r0 + 8;
#pragma unroll
        for (int nt = 0; nt < 8; nt++) {
            int cn = wc * 64 + nt * 8 + 2 * t4;
            float b0v = bx1[cn], b1v = bx1[cn + 1];
            *(__half2*)&sA[r0 * SA_STRH + cn] =
                __floats2half2_rn(silu_f(acc[mt][nt][0] + b0v), silu_f(acc[mt][nt][1] + b1v));
            *(__half2*)&sA[r1 * SA_STRH + cn] =
                __floats2half2_rn(silu_f(acc[mt][nt][2] + b0v), silu_f(acc[mt][nt][3] + b1v));
        }
    }
    for (int q = tid; q < 2048; q += 512) sAux[q] = Wxo[q];
    __syncthreads();

    // --- px partials: px[r] = s2[r] @ Wxo (4 column chunks) ---
    {
        int r = tid & 127, chunk = tid >> 7;
        float pa[8];
#pragma unroll
        for (int hh = 0; hh < 8; hh++) pa[hh] = 0.f;
        int c0 = chunk * 64;
        for (int c = c0; c < c0 + 64; c++) {
            float v = __half2float(sA[r * SA_STRH + c]);
#pragma unroll
            for (int hh = 0; hh < 8; hh++) pa[hh] += v * sAux[c * 8 + hh];
        }
#pragma unroll
        for (int hh = 0; hh < 8; hh++) pxp[(chunk * 128 + r) * 8 + hh] = pa[hh];
    }
    __syncthreads();
    if (tid < 128) {
#pragma unroll
        for (int hh = 0; hh < 8; hh++)
            pxp[tid * 8 + hh] = pxp[tid * 8 + hh] + pxp[(128 + tid) * 8 + hh]
                              + pxp[(256 + tid) * 8 + hh] + pxp[(384 + tid) * 8 + hh] + bxo[hh];
    }
    __syncthreads();

    // --- shift partials ---
    if (tid < 48) {
        int half = tid / 24, q = tid % 24, hh = q / 3, d = q % 3;
        int ii = half ? i1 : i0;
        float accs = 0.f;
        for (int jl = 0; jl < TJ; jl++) {
            float dn  = xs_j[jl*24 + hh*3 + d] - xs_i[half*24 + hh*3 + d];
            float nrm = sqrtf(sqn_s[half*512 + jl*8 + hh] + 1e-8f) + 1.0f;
            accs += (dn / nrm) * pxp[(half * 64 + jl) * 8 + hh];
        }
        g_shift_part[(jt * N_NODES + ii) * 24 + q] = accs;
    }
}

// ---------------- K4: phi_h per node ----------------
__global__ void hnode_kernel(const float* __restrict__ h,
                             const float* __restrict__ Wh0, const float* __restrict__ bh0,
                             const float* __restrict__ Wh1, const float* __restrict__ bh1,
                             const float* __restrict__ Who, const float* __restrict__ bho,
                             float* __restrict__ out) {
    int n = blockIdx.x, t = threadIdx.x;
    __shared__ float sin_s[384];
    __shared__ float s1[256];
    __shared__ float s2[256];
    float mi = 0.f;
#pragma unroll
    for (int p = 0; p < JT; p++) mi += g_mi_part[(p * N_NODES + n) * MD + t];
    sin_s[t] = mi;
    if (t < HD) sin_s[256 + t] = h[n * HD + t];
    __syncthreads();
    {
        float a0=0,a1=0,a2=0,a3=0;
        for (int k = 0; k < 384; k += 4) {
            a0 += sin_s[k  ] * Wh0[(k  ) * 256 + t];
            a1 += sin_s[k+1] * Wh0[(k+1) * 256 + t];
            a2 += sin_s[k+2] * Wh0[(k+2) * 256 + t];
            a3 += sin_s[k+3] * Wh0[(k+3) * 256 + t];
        }
        s1[t] = silu_f(a0 + a1 + a2 + a3 + bh0[t]);
    }
    __syncthreads();
    {
        float a0=0,a1=0,a2=0,a3=0;
        for (int k = 0; k < 256; k += 4) {
            a0 += s1[k  ] * Wh1[(k  ) * 256 + t];
            a1 += s1[k+1] * Wh1[(k+1) * 256 + t];
            a2 += s1[k+2] * Wh1[(k+2) * 256 + t];
            a3 += s1[k+3] * Wh1[(k+3) * 256 + t];
        }
        s2[t] = silu_f(a0 + a1 + a2 + a3 + bh1[t]);
    }
    __syncthreads();
    if (t < HD) {
        float a0=0,a1=0,a2=0,a3=0;
        for (int k = 0; k < 256; k += 4) {
            a0 += s2[k  ] * Who[(k  ) * 128 + t];
            a1 += s2[k+1] * Who[(k+1) * 128 + t];
            a2 += s2[k+2] * Who[(k+2) * 128 + t];
            a3 += s2[k+3] * Who[(k+3) * 128 + t];
        }
        out[12288 + n * HD + t] = h[n * HD + t] + a0 + a1 + a2 + a3 + bho[t];
    }
}

// ---------------- K5: x_new ----------------
__global__ void xout_kernel(const float* __restrict__ x, float* __restrict__ out) {
    int idx = blockIdx.x * blockDim.x + threadIdx.x;
    if (idx < N_NODES * 24) {
        float s = 0.f;
#pragma unroll
        for (int p = 0; p < JT; p++) s += g_shift_part[p * N_NODES * 24 + idx];
        out[idx] = x[idx] + s / (float)(N_NODES - 1);
    }
}

// ---------------- launch ----------------
extern "C" void kernel_launch(void* const* d_in, const int* in_sizes, int n_in,
                              void* d_out, int out_size) {
    const float* x    = (const float*)d_in[0];
    const float* h    = (const float*)d_in[1];
    const float* We0  = (const float*)d_in[2];
    const float* be0  = (const float*)d_in[3];
    const float* We1  = (const float*)d_in[4];
    const float* be1  = (const float*)d_in[5];
    const float* Winf = (const float*)d_in[6];
    const float* binf = (const float*)d_in[7];
    const float* Wx0  = (const float*)d_in[8];
    const float* bx0  = (const float*)d_in[9];
    const float* Wx1  = (const float*)d_in[10];
    const float* bx1  = (const float*)d_in[11];
    const float* Wxo  = (const float*)d_in[12];
    const float* bxo  = (const float*)d_in[13];
    const float* Wh0  = (const float*)d_in[14];
    const float* bh0  = (const float*)d_in[15];
    const float* Wh1  = (const float*)d_in[16];
    const float* bh1  = (const float*)d_in[17];
    const float* Who  = (const float*)d_in[18];
    const float* bho  = (const float*)d_in[19];
    float* out = (float*)d_out;

    cudaFuncSetAttribute(edge_kernel, cudaFuncAttributeMaxDynamicSharedMemorySize,
                         EDGE_SMEM_BYTES);

    prep_kernel<<<192, 256>>>(We1, Wx0, Wx1);
    hc_kernel<<<N_NODES, 256>>>(x, h);
    uv_kernel<<<N_NODES, 256>>>(We0, be0);
    edge_kernel<<<dim3(JT, N_NODES / 2), 512, EDGE_SMEM_BYTES>>>(
        x, We0, be1, Winf, binf, bx0, bx1, Wxo, bxo);
    hnode_kernel<<<N_NODES, 256>>>(h, Wh0, bh0, Wh1, bh1, Who, bho, out);
    xout_kernel<<<48, 256>>>(x, out);
}